// round 17
// baseline (speedup 1.0000x reference)
#include <cuda_runtime.h>
#include <cuda_fp16.h>
#include <cuda_fp8.h>
#include <cstdint>

#define NE 8
#define NH 2048
#define NI 5632
#define NT 256
#define NG 128

#define BM 64
#define BN 64
#define BK 32
#define WA 40          // As row stride (halfs): 80B
#define WB 72          // Bs row stride (halfs): 144B
#define NSLOT 5

// dynamic smem layout (5-slot rings)
#define AS_SZ (NSLOT * BM * WA * 2)    // 25600
#define BR_SZ (NSLOT * BK * BN * 4)    // 40960
#define BS_SZ (NSLOT * BK * WB * 2)    // 23040
#define SMEM_TOTAL (AS_SZ + BR_SZ + BS_SZ)   // 89600

// ---------------- scratch (zero-init device globals; alloc-free) ----------------
__device__ int    g_count[NE];
__device__ int    g_ptok[NE * NT];
__device__ float  g_pgate[NE * NT];
__device__ __align__(256) __half g_act1[(size_t)NE * NT * NH];
__device__ __align__(256) __half g_act2[(size_t)NE * NT * NI];
__device__ __align__(256) float  g_fc1[(size_t)NE * NT * 2 * NI];

// ---------------- helpers ----------------
__device__ __forceinline__ uint32_t smem_u32(const void* p) {
    return (uint32_t)__cvta_generic_to_shared(p);
}
__device__ __forceinline__ void ldsm_x4(uint32_t* r, uint32_t addr) {
    asm volatile("ldmatrix.sync.aligned.m8n8.x4.shared.b16 {%0,%1,%2,%3}, [%4];\n"
                 : "=r"(r[0]), "=r"(r[1]), "=r"(r[2]), "=r"(r[3]) : "r"(addr));
}
__device__ __forceinline__ void ldsm_x4_t(uint32_t* r, uint32_t addr) {
    asm volatile("ldmatrix.sync.aligned.m8n8.x4.trans.shared.b16 {%0,%1,%2,%3}, [%4];\n"
                 : "=r"(r[0]), "=r"(r[1]), "=r"(r[2]), "=r"(r[3]) : "r"(addr));
}
__device__ __forceinline__ void mma16816(float* d, const uint32_t* a, const uint32_t* b) {
    asm volatile("mma.sync.aligned.m16n8k16.row.col.f32.f16.f16.f32 "
                 "{%0,%1,%2,%3}, {%4,%5,%6,%7}, {%8,%9}, {%0,%1,%2,%3};\n"
                 : "+f"(d[0]), "+f"(d[1]), "+f"(d[2]), "+f"(d[3])
                 : "r"(a[0]), "r"(a[1]), "r"(a[2]), "r"(a[3]), "r"(b[0]), "r"(b[1]));
}
__device__ __forceinline__ void cp16(uint32_t dst, const void* src) {
    asm volatile("cp.async.cg.shared.global [%0], [%1], 16;\n" :: "r"(dst), "l"(src));
}
#define CP_COMMIT asm volatile("cp.async.commit_group;\n" ::)
#define CP_WAIT3  asm volatile("cp.async.wait_group 3;\n" ::)
#define CP_WAIT2  asm volatile("cp.async.wait_group 2;\n" ::)
#define CP_WAIT1  asm volatile("cp.async.wait_group 1;\n" ::)
#define CP_WAIT0  asm volatile("cp.async.wait_group 0;\n" ::)

// clip(x/s, ±448) -> e4m3 (RN, satfinite) -> dequant (exact in fp16)
__device__ __forceinline__ __half qdq_h(float x, float s) {
    float y = x / s;
    y = fminf(fmaxf(y, -448.f), 448.f);
    __nv_fp8_storage_t q = __nv_cvt_float_to_fp8(y, __NV_SATFINITE, __NV_E4M3);
    __half_raw hr = __nv_cvt_fp8_to_halfraw(q, __NV_E4M3);
    return *reinterpret_cast<__half*>(&hr);
}

// ---------------- kernel 1: routing ----------------
__global__ void routing_kernel(const float* __restrict__ logits) {
    int t = threadIdx.x;
    if (t < NE) g_count[t] = 0;
    __syncthreads();
    float l[NE];
#pragma unroll
    for (int i = 0; i < NE; i++) l[i] = logits[t * NE + i];
    int i0 = 0;
#pragma unroll
    for (int i = 1; i < NE; i++) if (l[i] > l[i0]) i0 = i;
    int i1 = (i0 == 0) ? 1 : 0;
#pragma unroll
    for (int i = 0; i < NE; i++) if (i != i0 && l[i] > l[i1]) i1 = i;
    float e1 = expf(l[i1] - l[i0]);
    float w0 = 1.f / (1.f + e1);
    float w1 = e1 / (1.f + e1);
    int p0 = atomicAdd(&g_count[i0], 1);
    g_ptok[i0 * NT + p0] = t; g_pgate[i0 * NT + p0] = w0;
    int p1 = atomicAdd(&g_count[i1], 1);
    g_ptok[i1 * NT + p1] = t; g_pgate[i1 * NT + p1] = w1;
}

// ---------------- kernel 2: gather + qdq(s1) ----------------
__global__ void act1_kernel(const float* __restrict__ hidden, const float* __restrict__ s1v) {
    int b = blockIdx.x;
    int e = b >> 8, pos = b & 255;
    if (pos >= g_count[e]) return;       // padded rows stay zero
    int t = g_ptok[b];
    float s1 = s1v[e];
    const float* src = hidden + (size_t)t * NH;
    __half* dst = g_act1 + (size_t)b * NH;
    for (int j = threadIdx.x; j < NH; j += blockDim.x)
        dst[j] = qdq_h(src[j], s1);
}

// ---------------- depth-4 pipelined GEMM core (dynamic smem, 256 thr, BM=64) ----------------
// W[k][n] int32 row-stride NTOT; Ws[g][n]; A fp16.
// FC1: writes fp32 to g_fc1 (device symbol). !FC1: gated atomic scatter to out.
template<int KDIM, int NTOT, bool FC1>
__global__ void __launch_bounds__(256, 2) gemm_core(
    const int* __restrict__ W, const float* __restrict__ Ws,
    float* __restrict__ outp, const float* __restrict__ s2v)
{
    constexpr int KT = KDIM / BK;
    extern __shared__ __align__(16) char smraw[];
    __half (*As)[BM][WA] = reinterpret_cast<__half(*)[BM][WA]>(smraw);
    int    (*Br)[BK][BN] = reinterpret_cast<int(*)[BK][BN]>(smraw + AS_SZ);
    __half (*Bs)[BK][WB] = reinterpret_cast<__half(*)[BK][WB]>(smraw + AS_SZ + BR_SZ);

    const int e = blockIdx.z, mt = blockIdx.y, nb = blockIdx.x;
    const int cnt = g_count[e];
    const int m0 = mt * BM;
    if (m0 >= cnt) return;
    const int n0 = nb * BN;
    const int tid = threadIdx.x, lane = tid & 31, wid = tid >> 5;
    const int mw = wid >> 2, nw = wid & 3;   // 2 m-warps x 4 n-warps, warp tile 32x16

    const __half* Abase = (FC1 ? g_act1 : g_act2) + (size_t)(e * NT + m0) * KDIM;
    const int*    Wbase = W + (size_t)e * KDIM * NTOT + n0;
    const float*  sF = Ws + (size_t)e * (KDIM / NG) * NTOT + n0 + nw * 16 + (lane & 3) * 2;

    float mAcc[2][2][4], gAcc[2][2][4];
#pragma unroll
    for (int a = 0; a < 2; a++)
#pragma unroll
        for (int b = 0; b < 2; b++)
#pragma unroll
            for (int c = 0; c < 4; c++) { mAcc[a][b][c] = 0.f; gAcc[a][b][c] = 0.f; }

    // B ownership: thread owns row tid>>3, 8 ints at cols (tid&7)*8 (2 x 16B)
    const int brow = tid >> 3, bcol = (tid & 7) * 8;
    // A: 64x32 halfs = 256 x 16B chunks; 1 per thread
    const int arow = tid >> 2, acol = (tid & 3) * 8;

    auto stage = [&](int kt_, int sl) {
        const int k0 = kt_ * BK;
        cp16(smem_u32(&As[sl][arow][acol]), Abase + (size_t)arow * KDIM + k0 + acol);
#pragma unroll
        for (int i = 0; i < 2; i++)
            cp16(smem_u32(&Br[sl][brow][bcol + i * 4]),
                 Wbase + (size_t)(k0 + brow) * NTOT + bcol + i * 4);
    };
    auto convertB = [&](int sl) {       // own data only (visible after own wait_group)
        int4 v0 = *(const int4*)&Br[sl][brow][bcol];
        int4 v1 = *(const int4*)&Br[sl][brow][bcol + 4];
        __align__(16) __half h[8];
        h[0] = __int2half_rn(v0.x); h[1] = __int2half_rn(v0.y);
        h[2] = __int2half_rn(v0.z); h[3] = __int2half_rn(v0.w);
        h[4] = __int2half_rn(v1.x); h[5] = __int2half_rn(v1.y);
        h[6] = __int2half_rn(v1.z); h[7] = __int2half_rn(v1.w);
        *(uint4*)&Bs[sl][brow][bcol] = *(uint4*)h;
    };
    auto mmatile = [&](int sl) {
#pragma unroll
        for (int ks = 0; ks < 2; ks++) {
            uint32_t a[2][4], bf[4];
#pragma unroll
            for (int mi = 0; mi < 2; mi++)
                ldsm_x4(a[mi], smem_u32(&As[sl][mw * 32 + mi * 16 + (lane & 15)][ks * 16 + (lane >> 4) * 8]));
            ldsm_x4_t(bf, smem_u32(&Bs[sl][ks * 16 + (lane & 15)][nw * 16 + (lane >> 4) * 8]));
#pragma unroll
            for (int mi = 0; mi < 2; mi++)
#pragma unroll
                for (int nj = 0; nj < 2; nj++)
                    mma16816(gAcc[mi][nj], a[mi], &bf[nj * 2]);
        }
    };

    // prologue: stage tiles 0..3 (depth 4)
    stage(0, 0); CP_COMMIT;
    stage(1, 1); CP_COMMIT;
    stage(2, 2); CP_COMMIT;
    stage(3, 3); CP_COMMIT;
    CP_WAIT3;                 // tile0 complete (own copies)
    convertB(0);
    __syncthreads();          // As[0], Bs[0] visible

    int slC = 0, slC1 = 1, slS = 4;
    for (int kt = 0; kt < KT; kt++) {
        if (kt + 4 < KT) { stage(kt + 4, slS); CP_COMMIT; }
        mmatile(slC);
        if ((kt & 3) == 3) {          // fold group accumulators (NG = 4 k-tiles)
            const int g = kt >> 2;
#pragma unroll
            for (int nj = 0; nj < 2; nj++) {
                float2 s2_ = *(const float2*)(sF + (size_t)g * NTOT + nj * 8);
#pragma unroll
                for (int mi = 0; mi < 2; mi++) {
                    mAcc[mi][nj][0] += gAcc[mi][nj][0] * s2_.x;
                    mAcc[mi][nj][1] += gAcc[mi][nj][1] * s2_.y;
                    mAcc[mi][nj][2] += gAcc[mi][nj][2] * s2_.x;
                    mAcc[mi][nj][3] += gAcc[mi][nj][3] * s2_.y;
                    gAcc[mi][nj][0] = 0.f; gAcc[mi][nj][1] = 0.f;
                    gAcc[mi][nj][2] = 0.f; gAcc[mi][nj][3] = 0.f;
                }
            }
        }
        if (kt + 1 < KT) {
            if      (kt + 4 < KT) { CP_WAIT3; }
            else if (kt + 3 < KT) { CP_WAIT2; }
            else if (kt + 2 < KT) { CP_WAIT1; }
            else                  { CP_WAIT0; }
            convertB(slC1);            // own data — no barrier needed before
            __syncthreads();           // publish As/Bs[slC1] for next iter
        }
        slC = slC1;
        slC1 = (slC1 + 1 == NSLOT) ? 0 : slC1 + 1;
        slS  = (slS  + 1 == NSLOT) ? 0 : slS  + 1;
    }

    // epilogue
    if (FC1) {
#pragma unroll
        for (int mi = 0; mi < 2; mi++)
#pragma unroll
            for (int h8 = 0; h8 < 2; h8++) {
                int row = mw * 32 + mi * 16 + (lane >> 2) + h8 * 8;
                int m = m0 + row;
                if (m >= cnt) continue;
                float* orow = g_fc1 + (size_t)(e * NT + m) * NTOT + n0 + nw * 16;
#pragma unroll
                for (int nj = 0; nj < 2; nj++) {
                    float2 v = make_float2(mAcc[mi][nj][h8 * 2 + 0], mAcc[mi][nj][h8 * 2 + 1]);
                    *(float2*)(orow + nj * 8 + (lane & 3) * 2) = v;
                }
            }
    } else {
        const float s2 = s2v[e];
#pragma unroll
        for (int mi = 0; mi < 2; mi++)
#pragma unroll
            for (int h8 = 0; h8 < 2; h8++) {
                int row = mw * 32 + mi * 16 + (lane >> 2) + h8 * 8;
                int m = m0 + row;
                if (m >= cnt) continue;
                int tok = g_ptok[e * NT + m];
                float wgt = g_pgate[e * NT + m] * s2;
                float* od = outp + (size_t)tok * NTOT + n0 + nw * 16;
#pragma unroll
                for (int nj = 0; nj < 2; nj++) {
                    int col = nj * 8 + (lane & 3) * 2;
                    atomicAdd(od + col,     mAcc[mi][nj][h8 * 2 + 0] * wgt);
                    atomicAdd(od + col + 1, mAcc[mi][nj][h8 * 2 + 1] * wgt);
                }
            }
    }
}

// ---------------- silu + qdq(s2): g_fc1 -> g_act2 ----------------
__global__ void __launch_bounds__(256) silu_kernel(const float* __restrict__ s1v,
                                                   const float* __restrict__ s2v) {
    int b = blockIdx.x, e = b >> 8, pos = b & 255;
    if (pos >= g_count[e]) return;
    float s1 = s1v[e], s2 = s2v[e];
    const float* fr = g_fc1 + (size_t)b * (2 * NI);
    __half* orow = g_act2 + (size_t)b * NI;
    for (int j = threadIdx.x * 2; j < NI; j += 512) {
        float2 u2 = *(const float2*)(fr + j);
        float2 g2 = *(const float2*)(fr + NI + j);
        float u0 = u2.x * s1, u1 = u2.y * s1;
        float g0 = g2.x * s1, g1 = g2.y * s1;
        float h0 = u0 * g0 / (1.f + expf(-g0));
        float h1 = u1 * g1 / (1.f + expf(-g1));
        __half2 hq;
        hq.x = qdq_h(h0, s2);
        hq.y = qdq_h(h1, s2);
        *(__half2*)(orow + j) = hq;
    }
}

// ---------------- launch ----------------
extern "C" void kernel_launch(void* const* d_in, const int* in_sizes, int n_in,
                              void* d_out, int out_size) {
    const float* hidden = nullptr;
    const float* logits = nullptr;
    const int*   w1     = nullptr;
    const int*   w2     = nullptr;
    const float* w1s    = nullptr;
    const float* w2s    = nullptr;
    const float* s1     = nullptr;
    const float* s2     = nullptr;

    for (int i = 0; i < n_in; i++) {
        switch (in_sizes[i]) {
            case 524288:    hidden = (const float*)d_in[i]; break;
            case 2048:      logits = (const float*)d_in[i]; break;
            case 184549376: w1     = (const int*)d_in[i];   break;
            case 92274688:  w2     = (const int*)d_in[i];   break;
            case 1441792:   w1s    = (const float*)d_in[i]; break;
            case 720896:    w2s    = (const float*)d_in[i]; break;
            case 8:
                if (!s1) s1 = (const float*)d_in[i];
                else     s2 = (const float*)d_in[i];
                break;
            default: break;
        }
    }
    float* out = (float*)d_out;

    cudaFuncSetAttribute(gemm_core<NH, 2 * NI, true>,
                         cudaFuncAttributeMaxDynamicSharedMemorySize, SMEM_TOTAL);
    cudaFuncSetAttribute(gemm_core<NI, NH, false>,
                         cudaFuncAttributeMaxDynamicSharedMemorySize, SMEM_TOTAL);

    cudaMemsetAsync(out, 0, (size_t)out_size * sizeof(float));
    routing_kernel<<<1, NT>>>(logits);
    act1_kernel<<<NE * NT, 256>>>(hidden, s1);
    gemm_core<NH, 2 * NI, true><<<dim3((2 * NI) / BN, 4, NE), 256, SMEM_TOTAL>>>(w1, w1s, nullptr, nullptr);
    silu_kernel<<<NE * NT, 256>>>(s1, s2);
    gemm_core<NI, NH, false><<<dim3(NH / BN, 4, NE), 256, SMEM_TOTAL>>>(w2, w2s, out, s2);
}